// round 15
// baseline (speedup 1.0000x reference)
#include <cuda_runtime.h>

// SNN: B=1024, T=4096, 6 -> 10 -> 27 LIF (subtract reset).
// Producer/consumer warp pairs (one element each), flag-synced (acq/rel SMEM
// sequence counters -- named-barrier credit schemes self-fire and deadlock):
//   A-warp: phaseA (warp-private staging) + layer-1 + lagged ballot;
//           masks -> 4-deep SMEM ring; st.release prod=k+1 per chunk.
//   B-warp: ld.acquire spin on prod; table fetch + layer-2; st.release cons.
//   A back-pressures on cons with 3 chunks of credit -> warps decouple.
// 16 warps/CTA x 128 CTAs = 4 warps/SMSP on all 128 SMs.

#define T_LEN 4096
#define BETA 0.9f
#define CTA_THREADS 512
#define N_CTAS 128
#define PAIRS 8

#define TABLE_FLOATS (1024 * 27 + 32)  /* rows 0..1023 + zero row 1024 */
#define STG_STRIDE 14
#define STG_BANK 480                    /* >= 31*14+31+1 */
#define STG_PER_PAIR (2 * STG_BANK)
#define MB_BANK 36                      /* u32: 32 masks + final + pad */
#define MB_BANKS 4                      /* ring depth (credit 3) */
#define MB_PER_PAIR (MB_BANKS * MB_BANK)
#define MASK_U32 (PAIRS * MB_PER_PAIR)  /* 1152 */
#define FLAG_U32 (PAIRS * 8)            /* prod @ pair*8, cons @ pair*8+4 */
#define SMEM_FLOATS (TABLE_FLOATS + MASK_U32 + FLAG_U32 + PAIRS * STG_PER_PAIR)
#define SMEM_BYTES (SMEM_FLOATS * 4)    /* 146,304 B */

typedef unsigned long long u64;

__device__ __forceinline__ u64 pack2(float lo, float hi) {
    u64 r; asm("mov.b64 %0,{%1,%2};" : "=l"(r) : "f"(lo), "f"(hi)); return r;
}
__device__ __forceinline__ u64 mul2(u64 a, u64 b) {
    u64 r; asm("mul.rn.f32x2 %0,%1,%2;" : "=l"(r) : "l"(a), "l"(b)); return r;
}
__device__ __forceinline__ u64 fma2(u64 a, u64 b, u64 c) {
    u64 r; asm("fma.rn.f32x2 %0,%1,%2,%3;" : "=l"(r) : "l"(a), "l"(b), "l"(c)); return r;
}
__device__ __forceinline__ u64 add2(u64 a, u64 b) {
    u64 r; asm("add.rn.f32x2 %0,%1,%2;" : "=l"(r) : "l"(a), "l"(b)); return r;
}
__device__ __forceinline__ float fset_gt1(float a) {
    float r; asm("set.gt.f32.f32 %0,%1,0f3F800000;" : "=f"(r) : "f"(a)); return r;
}
__device__ __forceinline__ unsigned ld_acq(const unsigned* p) {
    unsigned v, a = (unsigned)__cvta_generic_to_shared(p);
    asm volatile("ld.acquire.cta.shared.u32 %0, [%1];" : "=r"(v) : "r"(a) : "memory");
    return v;
}
__device__ __forceinline__ void st_rel(unsigned* p, unsigned v) {
    unsigned a = (unsigned)__cvta_generic_to_shared(p);
    asm volatile("st.release.cta.shared.u32 [%0], %1;" :: "r"(a), "r"(v) : "memory");
}

// Phase A: 10 neuron currents for this lane's timestep, f32x2-packed.
// Per-half rounding == scalar; ascending-k chain from a mul, then +b1
// == cublas accumulation order (reference-exact).
__device__ __forceinline__ void phaseA_store(const float xv[6],
                                             const u64 w12r[5][6],
                                             const u64 b12r[5],
                                             float* wb, int lane)
{
    u64 xx[6];
#pragma unroll
    for (int c = 0; c < 6; c++) xx[c] = pack2(xv[c], xv[c]);
#pragma unroll
    for (int np = 0; np < 5; np++) {
        u64 a = mul2(xx[0], w12r[np][0]);
#pragma unroll
        for (int c = 1; c < 6; c++)
            a = fma2(xx[c], w12r[np][c], a);
        a = add2(a, b12r[np]);
        *reinterpret_cast<u64*>(&wb[lane * STG_STRIDE + 2 * np]) = a;
    }
}

__device__ __forceinline__ void fetch4(uint4 mv, const float* trow, float f[4])
{
    f[0] = trow[mv.x * 27u];
    f[1] = trow[mv.y * 27u];
    f[2] = trow[mv.z * 27u];
    f[3] = trow[mv.w * 27u];
}
// 4 layer-2 steps: mem = fma(beta,mem,cur) - s ; s = (mem>1) as float.
__device__ __forceinline__ void l2_consume4(const float c[4], float& m2, float& s2)
{
#pragma unroll
    for (int i = 0; i < 4; i++) {
        float a2 = fmaf(BETA, m2, c[i]);
        m2 = __fsub_rn(a2, s2);
        s2 = fset_gt1(m2);
    }
}
// One chunk of layer-2: 8 sub-batches, ping-pong (no carry copies).
// fB carries 4 pending currents across chunks.
__device__ __forceinline__ void l2_chunk(const unsigned* mrow, const float* trow,
                                         float& m2, float& s2,
                                         float (&fA)[4], float (&fB)[4])
{
#pragma unroll
    for (int sb = 0; sb < 8; sb += 2) {
        uint4 mv0 = *reinterpret_cast<const uint4*>(mrow + sb * 4);
        fetch4(mv0, trow, fA);
        l2_consume4(fB, m2, s2);
        uint4 mv1 = *reinterpret_cast<const uint4*>(mrow + sb * 4 + 4);
        fetch4(mv1, trow, fB);
        l2_consume4(fA, m2, s2);
    }
}

__global__ void __launch_bounds__(CTA_THREADS, 1)
snn_kernel(const float* __restrict__ x, const float* __restrict__ W1,
           const float* __restrict__ b1, const float* __restrict__ W2,
           const float* __restrict__ b2, float* __restrict__ out)
{
    extern __shared__ float smem[];
    float* table = smem;                                  // [1024][27] + zero row
    unsigned* maskall = (unsigned*)(smem + TABLE_FLOATS); // [PAIRS][4][36]
    unsigned* flags = maskall + MASK_U32;                 // [PAIRS][8]
    float* stg = smem + TABLE_FLOATS + MASK_U32 + FLAG_U32;

    const int tid  = threadIdx.x;
    const int wid  = tid >> 5;
    const int lane = tid & 31;
    const bool isA = (wid < PAIRS);
    const int pair = wid & (PAIRS - 1);
    const int b = blockIdx.x * PAIRS + pair;

    const float* xb = x + (size_t)b * (6 * T_LEN);

    // Layer-2 lookup table: ascending-n accumulation == reference fma-dot
    // with 0/1 spikes (adding 0.0f is exact).
    for (int e = tid; e < 1024 * 27; e += CTA_THREADS) {
        int v = e / 27;
        int m = e - v * 27;
        float acc = 0.0f;
#pragma unroll
        for (int n = 0; n < 10; n++)
            if (v & (1 << n)) acc = __fadd_rn(acc, W2[m * 10 + n]);
        table[e] = __fadd_rn(acc, b2[m]);
    }
    for (int i = 1024 * 27 + tid; i < TABLE_FLOATS; i += CTA_THREADS)
        table[i] = 0.0f;  // zero row 1024
    if (tid < FLAG_U32) flags[tid] = 0;

    unsigned* prod = flags + pair * 8;
    unsigned* cons = flags + pair * 8 + 4;
    unsigned* mbase = maskall + pair * MB_PER_PAIR;
    float* stg0 = stg + pair * STG_PER_PAIR;
    float* stg1 = stg0 + STG_BANK;

    if (isA) {
        // ====== A-warp: phaseA + layer-1 producer (self-contained) ======
        u64 w12r[5][6], b12r[5];
#pragma unroll
        for (int np = 0; np < 5; np++) {
            b12r[np] = pack2(b1[2 * np], b1[2 * np + 1]);
#pragma unroll
            for (int c = 0; c < 6; c++)
                w12r[np][c] = pack2(W1[(2 * np) * 6 + c], W1[(2 * np + 1) * 6 + c]);
        }
        float xv[6];
#pragma unroll
        for (int c = 0; c < 6; c++) xv[c] = xb[c * T_LEN + lane];
        phaseA_store(xv, w12r, b12r, stg0, lane);  // chunk 0 -> bank 0
#pragma unroll
        for (int c = 0; c < 6; c++) xv[c] = xb[c * T_LEN + 32 + lane];

        __syncthreads();  // table + flags visible everywhere

        float m1 = 0.0f, s1 = 0.0f;
        bool pd = (lane == 10);        // ballot(step -1) = 1<<10 -> zero row
        const bool vlane = (lane < 10);
        const bool st_lane = (lane == 0);

#pragma unroll 1
        for (int k = 0; k < 128; k++) {
            // phaseA for chunk k+1 (warp-private staging; no sync needed)
            if (k < 127) {
                float* wb = ((k + 1) & 1) ? stg1 : stg0;
                phaseA_store(xv, w12r, b12r, wb, lane);
                int kk = (k + 2 < 128) ? k + 2 : 127;
#pragma unroll
                for (int c = 0; c < 6; c++)
                    xv[c] = xb[c * T_LEN + kk * 32 + lane];
            }
            // backpressure: ring slot (k&3) reusable once B consumed chunk k-4
            if (k >= 4 && st_lane)
                while ((int)ld_acq(cons) < k - 3) {}
            __syncwarp();

            const float* rb = (k & 1) ? stg1 : stg0;
            unsigned* mrow = mbase + (k & 3) * MB_BANK;
#pragma unroll
            for (int sb = 0; sb < 8; sb++) {
                float c1r[4];
#pragma unroll
                for (int i = 0; i < 4; i++)
                    c1r[i] = rb[(sb * 4 + i) * STG_STRIDE + lane];
                unsigned mr[4];
#pragma unroll
                for (int i = 0; i < 4; i++) {
                    mr[i] = __ballot_sync(0xffffffffu, pd);  // lagged: no stall
                    float a1 = fmaf(BETA, m1, c1r[i]);
                    m1 = __fsub_rn(a1, s1);
                    s1 = fset_gt1(m1);
                    pd = (m1 > 1.0f) && vlane;
                }
                if (st_lane)
                    *reinterpret_cast<uint4*>(mrow + sb * 4) =
                        make_uint4(mr[0], mr[1], mr[2], mr[3]);
            }
            if (k == 127) {  // final mask (step 4095) before publishing
                unsigned vf = __ballot_sync(0xffffffffu, pd);
                if (st_lane) mrow[32] = vf;
            }
            if (st_lane) st_rel(prod, (unsigned)(k + 1));  // publish chunk k
        }
    } else {
        // ====== B-warp: layer-2 consumer ======
        __syncthreads();

        const float* trow = table + lane;
        float m2 = 0.0f, s2 = 0.0f;
        float fA[4], fB[4] = {0.0f, 0.0f, 0.0f, 0.0f};  // 4 fake zero steps

#pragma unroll 1
        for (int k = 0; k < 128; k++) {
            if (lane == 0)
                while ((int)ld_acq(prod) < k + 1) {}
            __syncwarp();
            const unsigned* mrow = mbase + (k & 3) * MB_BANK;
            l2_chunk(mrow, trow, m2, s2, fA, fB);
            if (lane == 0) st_rel(cons, (unsigned)(k + 1));
            __syncwarp();
        }
        // Epilogue: pending steps 4091..4094 + final mask (slot 32, bank 3)
        {
            const unsigned* mrow = mbase + 3 * MB_BANK;
            l2_consume4(fB, m2, s2);
            float ff = trow[mrow[32] * 27u];  // mask(step 4095)
            float a2 = fmaf(BETA, m2, ff);
            m2 = __fsub_rn(a2, s2);
            s2 = fset_gt1(m2);
        }
        if (lane < 27)
            out[b * 27 + lane] = s2;
    }
}

extern "C" void kernel_launch(void* const* d_in, const int* in_sizes, int n_in,
                              void* d_out, int out_size)
{
    const float* x  = (const float*)d_in[0];
    const float* W1 = (const float*)d_in[1];
    const float* b1 = (const float*)d_in[2];
    const float* W2 = (const float*)d_in[3];
    const float* b2 = (const float*)d_in[4];
    float* out = (float*)d_out;

    cudaFuncSetAttribute(snn_kernel, cudaFuncAttributeMaxDynamicSharedMemorySize,
                         SMEM_BYTES);

    snn_kernel<<<N_CTAS, CTA_THREADS, SMEM_BYTES>>>(x, W1, b1, W2, b2, out);
}

// round 16
// speedup vs baseline: 1.3912x; 1.3912x over previous
#include <cuda_runtime.h>

// SNN: B=1024, T=4096, 6 -> 10 -> 27 LIF (subtract reset).
// FOUR-warp groups serving TWO elements, all four warps on ONE SMSP
// (wids {g, g+4, g+8, g+12} -> wid%4 == g), rendezvous bar.sync(1+g,128)/chunk:
//   role0 A : layer-1 SIMD-2 (lanes 0-9 = e0, 16-25 = e1) + lagged ballot;
//             combined masks -> 2-bank SMEM ring (STS.128 per 4 steps)
//   role1/2 : B0/B1 - mask bitfield extract + table fetch + layer-2 + output
//   role3 W3: phaseA staging for BOTH elements + x prefetch
// 16 warps/CTA x 128 CTAs = 4 warps/SMSP on all 128 SMs.

#define T_LEN 4096
#define BETA 0.9f
#define CTA_THREADS 512
#define N_CTAS 128
#define GROUPS 4

#define TABLE_FLOATS (1024 * 27 + 32)   /* rows 0..1023 + zero row 1024 */
#define STG_STRIDE 34                    /* even: aligned STS.64; reads ok */
#define STG_BANK (32 * STG_STRIDE)       /* 1088 floats */
#define STG_PER_GROUP (2 * STG_BANK)
#define MB_BANK 36                       /* u32: 32 masks + final + pad */
#define MB_PER_GROUP (2 * MB_BANK)
#define MASK_U32 (GROUPS * MB_PER_GROUP)
#define SMEM_FLOATS (TABLE_FLOATS + MASK_U32 + GROUPS * STG_PER_GROUP)
#define SMEM_BYTES (SMEM_FLOATS * 4)     /* 146,688 B */

typedef unsigned long long u64;

__device__ __forceinline__ u64 pack2(float lo, float hi) {
    u64 r; asm("mov.b64 %0,{%1,%2};" : "=l"(r) : "f"(lo), "f"(hi)); return r;
}
__device__ __forceinline__ u64 mul2(u64 a, u64 b) {
    u64 r; asm("mul.rn.f32x2 %0,%1,%2;" : "=l"(r) : "l"(a), "l"(b)); return r;
}
__device__ __forceinline__ u64 fma2(u64 a, u64 b, u64 c) {
    u64 r; asm("fma.rn.f32x2 %0,%1,%2,%3;" : "=l"(r) : "l"(a), "l"(b), "l"(c)); return r;
}
__device__ __forceinline__ u64 add2(u64 a, u64 b) {
    u64 r; asm("add.rn.f32x2 %0,%1,%2;" : "=l"(r) : "l"(a), "l"(b)); return r;
}
__device__ __forceinline__ float fset_gt1(float a) {
    float r; asm("set.gt.f32.f32 %0,%1,0f3F800000;" : "=f"(r) : "f"(a)); return r;
}
#define GROUP_BAR(g) asm volatile("bar.sync %0, 128;" :: "r"(1 + (g)) : "memory")

// Phase A: 10 neuron currents for this lane's timestep into staging columns
// [base, base+10). Per-half f32x2 rounding == scalar; ascending-k chain from a
// mul, then +b1 == cublas accumulation order (reference-exact).
__device__ __forceinline__ void phaseA_store(const float xv[6],
                                             const u64 w12r[5][6],
                                             const u64 b12r[5],
                                             float* wb, int lane, int base)
{
    u64 xx[6];
#pragma unroll
    for (int c = 0; c < 6; c++) xx[c] = pack2(xv[c], xv[c]);
#pragma unroll
    for (int np = 0; np < 5; np++) {
        u64 a = mul2(xx[0], w12r[np][0]);
#pragma unroll
        for (int c = 1; c < 6; c++)
            a = fma2(xx[c], w12r[np][c], a);
        a = add2(a, b12r[np]);
        *reinterpret_cast<u64*>(&wb[lane * STG_STRIDE + base + 2 * np]) = a;
    }
}

// Fetch 4 layer-2 currents from combined masks (bitfield at `shift`).
__device__ __forceinline__ void fetch4s(uint4 mv, const float* trow, int shift,
                                        float f[4])
{
    f[0] = trow[((mv.x >> shift) & 0x7FFu) * 27u];
    f[1] = trow[((mv.y >> shift) & 0x7FFu) * 27u];
    f[2] = trow[((mv.z >> shift) & 0x7FFu) * 27u];
    f[3] = trow[((mv.w >> shift) & 0x7FFu) * 27u];
}
// 4 layer-2 steps: mem = fma(beta,mem,cur) - s ; s = (mem>1) as float.
__device__ __forceinline__ void l2_consume4(const float c[4], float& m2, float& s2)
{
#pragma unroll
    for (int i = 0; i < 4; i++) {
        float a2 = fmaf(BETA, m2, c[i]);
        m2 = __fsub_rn(a2, s2);
        s2 = fset_gt1(m2);
    }
}
// One chunk of layer-2: 8 sub-batches, ping-pong (no carry copies).
// fB carries 4 pending currents across chunks.
__device__ __forceinline__ void l2_chunk(const unsigned* mrow, const float* trow,
                                         int shift, float& m2, float& s2,
                                         float (&fA)[4], float (&fB)[4])
{
#pragma unroll
    for (int sb = 0; sb < 8; sb += 2) {
        uint4 mv0 = *reinterpret_cast<const uint4*>(mrow + sb * 4);
        fetch4s(mv0, trow, shift, fA);
        l2_consume4(fB, m2, s2);
        uint4 mv1 = *reinterpret_cast<const uint4*>(mrow + sb * 4 + 4);
        fetch4s(mv1, trow, shift, fB);
        l2_consume4(fA, m2, s2);
    }
}

__global__ void __launch_bounds__(CTA_THREADS, 1)
snn_kernel(const float* __restrict__ x, const float* __restrict__ W1,
           const float* __restrict__ b1, const float* __restrict__ W2,
           const float* __restrict__ b2, float* __restrict__ out)
{
    extern __shared__ float smem[];
    float* table = smem;                                  // [1024][27] + zero row
    unsigned* maskall = (unsigned*)(smem + TABLE_FLOATS); // [GROUPS][2][36]
    float* stg = smem + TABLE_FLOATS + MASK_U32;          // [GROUPS][2][32*34]

    const int tid  = threadIdx.x;
    const int wid  = tid >> 5;
    const int lane = tid & 31;
    const int group = wid & 3;        // wid%4 == SMSP -> whole group on one SMSP
    const int role  = wid >> 2;       // 0=A, 1=B0, 2=B1, 3=W3

    // Layer-2 lookup table: ascending-n accumulation == reference fma-dot
    // with 0/1 spikes (adding 0.0f is exact).
    for (int e = tid; e < 1024 * 27; e += CTA_THREADS) {
        int v = e / 27;
        int m = e - v * 27;
        float acc = 0.0f;
#pragma unroll
        for (int n = 0; n < 10; n++)
            if (v & (1 << n)) acc = __fadd_rn(acc, W2[m * 10 + n]);
        table[e] = __fadd_rn(acc, b2[m]);
    }
    for (int i = 1024 * 27 + tid; i < TABLE_FLOATS; i += CTA_THREADS)
        table[i] = 0.0f;  // zero row 1024

    unsigned* mbase = maskall + group * MB_PER_GROUP;
    float* stg0 = stg + group * STG_PER_GROUP;
    float* stg1 = stg0 + STG_BANK;
    const int e0 = (blockIdx.x * GROUPS + group) * 2;

    // ---- W3 state + prologue (staging chunk 0 must precede __syncthreads)
    u64 w12r[5][6], b12r[5];
    float xv0[6], xv1[6];
    if (role == 3) {
#pragma unroll
        for (int np = 0; np < 5; np++) {
            b12r[np] = pack2(b1[2 * np], b1[2 * np + 1]);
#pragma unroll
            for (int c = 0; c < 6; c++)
                w12r[np][c] = pack2(W1[(2 * np) * 6 + c], W1[(2 * np + 1) * 6 + c]);
        }
        const float* xa = x + (size_t)e0 * (6 * T_LEN);
        const float* xb = x + (size_t)(e0 + 1) * (6 * T_LEN);
#pragma unroll
        for (int c = 0; c < 6; c++) {
            xv0[c] = xa[c * T_LEN + lane];
            xv1[c] = xb[c * T_LEN + lane];
        }
        phaseA_store(xv0, w12r, b12r, stg0, lane, 0);   // chunk 0, elem 0
        phaseA_store(xv1, w12r, b12r, stg0, lane, 16);  // chunk 0, elem 1
#pragma unroll
        for (int c = 0; c < 6; c++) {
            xv0[c] = xa[c * T_LEN + 32 + lane];
            xv1[c] = xb[c * T_LEN + 32 + lane];
        }
    }
    __syncthreads();  // table + chunk-0 staging visible

    if (role == 0) {
        // ============ A: layer 1 SIMD-2 producer ============
        float m1 = 0.0f, s1 = 0.0f;
        const bool vlane = (lane < 10) || (lane >= 16 && lane < 26);
        // ballot(step -1) = (1<<10)|(1<<26): both extracted fields = 1024
        bool pd = (lane == 10) || (lane == 26);
        const bool st_lane = (lane == 0);

#pragma unroll 1
        for (int k = 0; k < 128; k++) {
            const float* rb = (k & 1) ? stg1 : stg0;
            unsigned* mrow = mbase + (k & 1) * MB_BANK;
#pragma unroll
            for (int sb = 0; sb < 8; sb++) {
                float c1r[4];
#pragma unroll
                for (int i = 0; i < 4; i++)
                    c1r[i] = rb[(sb * 4 + i) * STG_STRIDE + lane];
                unsigned mr[4];
#pragma unroll
                for (int i = 0; i < 4; i++) {
                    mr[i] = __ballot_sync(0xffffffffu, pd);  // lagged: no stall
                    float a1 = fmaf(BETA, m1, c1r[i]);
                    m1 = __fsub_rn(a1, s1);
                    s1 = fset_gt1(m1);
                    pd = (m1 > 1.0f) && vlane;
                }
                if (st_lane)
                    *reinterpret_cast<uint4*>(mrow + sb * 4) =
                        make_uint4(mr[0], mr[1], mr[2], mr[3]);
            }
            if (k == 127) {  // final mask (step 4095)
                unsigned vf = __ballot_sync(0xffffffffu, pd);
                if (st_lane) mrow[32] = vf;
            }
            GROUP_BAR(group);
        }
    } else if (role == 3) {
        // ============ W3: phaseA producer for both elements ============
        const float* xa = x + (size_t)e0 * (6 * T_LEN);
        const float* xb = x + (size_t)(e0 + 1) * (6 * T_LEN);
#pragma unroll 1
        for (int k = 0; k < 128; k++) {
            if (k < 127) {
                float* wb = ((k + 1) & 1) ? stg1 : stg0;
                phaseA_store(xv0, w12r, b12r, wb, lane, 0);
                phaseA_store(xv1, w12r, b12r, wb, lane, 16);
                int kk = (k + 2 < 128) ? k + 2 : 127;  // clamped prefetch
#pragma unroll
                for (int c = 0; c < 6; c++) {
                    xv0[c] = xa[c * T_LEN + kk * 32 + lane];
                    xv1[c] = xb[c * T_LEN + kk * 32 + lane];
                }
            }
            GROUP_BAR(group);
        }
    } else {
        // ============ B0/B1: layer-2 consumer for one element ============
        const int erole = role - 1;           // 0 or 1
        const int shift = 16 * erole;
        const int b = e0 + erole;
        const float* trow = table + lane;
        float m2 = 0.0f, s2 = 0.0f;
        float fA[4], fB[4] = {0.0f, 0.0f, 0.0f, 0.0f};  // 4 fake zero steps

#pragma unroll 1
        for (int k = 0; k < 128; k++) {
            if (k >= 1) {
                const unsigned* mrow = mbase + ((k - 1) & 1) * MB_BANK;
                l2_chunk(mrow, trow, shift, m2, s2, fA, fB);
            }
            GROUP_BAR(group);
        }
        // Epilogue: chunk 127 (bank 1) + pending + final mask (slot 32)
        {
            const unsigned* mrow = mbase + MB_BANK;
            l2_chunk(mrow, trow, shift, m2, s2, fA, fB);
            l2_consume4(fB, m2, s2);  // steps 4091..4094
            float ff = trow[((mrow[32] >> shift) & 0x7FFu) * 27u];  // mask(4095)
            float a2 = fmaf(BETA, m2, ff);
            m2 = __fsub_rn(a2, s2);
            s2 = fset_gt1(m2);
        }
        if (lane < 27)
            out[b * 27 + lane] = s2;
    }
}

extern "C" void kernel_launch(void* const* d_in, const int* in_sizes, int n_in,
                              void* d_out, int out_size)
{
    const float* x  = (const float*)d_in[0];
    const float* W1 = (const float*)d_in[1];
    const float* b1 = (const float*)d_in[2];
    const float* W2 = (const float*)d_in[3];
    const float* b2 = (const float*)d_in[4];
    float* out = (float*)d_out;

    cudaFuncSetAttribute(snn_kernel, cudaFuncAttributeMaxDynamicSharedMemorySize,
                         SMEM_BYTES);

    snn_kernel<<<N_CTAS, CTA_THREADS, SMEM_BYTES>>>(x, W1, b1, W2, b2, out);
}

// round 17
// speedup vs baseline: 1.6067x; 1.1549x over previous
#include <cuda_runtime.h>

// SNN: B=1024, T=4096, 6 -> 10 -> 27 LIF (subtract reset).
// R12 topology (2-warp pairs, one element each, 2 independent pairs per SMSP,
// pairwise bar.sync rendezvous) + trims:
//  - neuron-major staging [10][68]: A reads c1 via LDS.128 (4 steps at once)
//  - 64-step chunks: half the barriers / mask traffic
//   A-warp: layer-1 recurrence + lagged ballot -> mask bank (STS.128/4 steps)
//   B-warp: phaseA staging (10 STS.32/lane-col) + table fetch + layer-2 + out
// 16 warps/CTA x 128 CTAs = 4 warps/SMSP on all 128 SMs.

#define T_LEN 4096
#define BETA 0.9f
#define CTA_THREADS 512
#define N_CTAS 128
#define PAIRS 8
#define NCHUNK 64                        /* 64 steps per chunk */

#define TABLE_FLOATS (1024 * 27 + 32)    /* rows 0..1023 + zero row 1024 */
#define STG_ROW 68                       /* 64 steps + pad, 16B multiple */
#define STG_BANK (10 * STG_ROW)          /* 680 floats */
#define STG_PER_PAIR (2 * STG_BANK)
#define MB_BANK 68                       /* u32: 64 masks + final + pad */
#define MB_PER_PAIR (2 * MB_BANK)
#define MASK_U32 (PAIRS * MB_PER_PAIR)   /* 1088 */
#define SMEM_FLOATS (TABLE_FLOATS + MASK_U32 + PAIRS * STG_PER_PAIR)
#define SMEM_BYTES (SMEM_FLOATS * 4)     /* 158,592 B */

typedef unsigned long long u64;

__device__ __forceinline__ u64 pack2(float lo, float hi) {
    u64 r; asm("mov.b64 %0,{%1,%2};" : "=l"(r) : "f"(lo), "f"(hi)); return r;
}
__device__ __forceinline__ void unpack2(u64 a, float& lo, float& hi) {
    asm("mov.b64 {%0,%1},%2;" : "=f"(lo), "=f"(hi) : "l"(a));
}
__device__ __forceinline__ u64 mul2(u64 a, u64 b) {
    u64 r; asm("mul.rn.f32x2 %0,%1,%2;" : "=l"(r) : "l"(a), "l"(b)); return r;
}
__device__ __forceinline__ u64 fma2(u64 a, u64 b, u64 c) {
    u64 r; asm("fma.rn.f32x2 %0,%1,%2,%3;" : "=l"(r) : "l"(a), "l"(b), "l"(c)); return r;
}
__device__ __forceinline__ u64 add2(u64 a, u64 b) {
    u64 r; asm("add.rn.f32x2 %0,%1,%2;" : "=l"(r) : "l"(a), "l"(b)); return r;
}
__device__ __forceinline__ float fset_gt1(float a) {
    float r; asm("set.gt.f32.f32 %0,%1,0f3F800000;" : "=f"(r) : "f"(a)); return r;
}
#define PAIR_BAR(pid) asm volatile("bar.sync %0, 64;" :: "r"(1 + (pid)) : "memory")

// Phase A into NEURON-MAJOR staging: this lane's timestep = column `col`.
// Computes neurons (2np, 2np+1) packed in f32x2 (per-half rounding == scalar;
// ascending-k chain from a mul, then +b1 == cublas accumulation order), then
// stores the two halves to rows 2np / 2np+1 at column col (conflict-free).
__device__ __forceinline__ void phaseA_nm(const float xv[6],
                                          const u64 w12r[5][6],
                                          const u64 b12r[5],
                                          float* bank, int col)
{
    u64 xx[6];
#pragma unroll
    for (int c = 0; c < 6; c++) xx[c] = pack2(xv[c], xv[c]);
#pragma unroll
    for (int np = 0; np < 5; np++) {
        u64 a = mul2(xx[0], w12r[np][0]);
#pragma unroll
        for (int c = 1; c < 6; c++)
            a = fma2(xx[c], w12r[np][c], a);
        a = add2(a, b12r[np]);
        float lo, hi;
        unpack2(a, lo, hi);
        bank[(2 * np) * STG_ROW + col]     = lo;
        bank[(2 * np + 1) * STG_ROW + col] = hi;
    }
}

// Fetch 4 layer-2 currents for 4 masks.
__device__ __forceinline__ void fetch4(uint4 mv, const float* trow, float f[4])
{
    f[0] = trow[mv.x * 27u];
    f[1] = trow[mv.y * 27u];
    f[2] = trow[mv.z * 27u];
    f[3] = trow[mv.w * 27u];
}
// 4 layer-2 steps: mem = fma(beta,mem,cur) - s ; s = (mem>1) as float.
__device__ __forceinline__ void l2_consume4(const float c[4], float& m2, float& s2)
{
#pragma unroll
    for (int i = 0; i < 4; i++) {
        float a2 = fmaf(BETA, m2, c[i]);
        m2 = __fsub_rn(a2, s2);
        s2 = fset_gt1(m2);
    }
}
// One 64-step chunk of layer-2: 16 sub-batches, ping-pong carries.
__device__ __forceinline__ void l2_chunk(const unsigned* mrow, const float* trow,
                                         float& m2, float& s2,
                                         float (&fA)[4], float (&fB)[4])
{
#pragma unroll
    for (int sb = 0; sb < 16; sb += 2) {
        uint4 mv0 = *reinterpret_cast<const uint4*>(mrow + sb * 4);
        fetch4(mv0, trow, fA);
        l2_consume4(fB, m2, s2);
        uint4 mv1 = *reinterpret_cast<const uint4*>(mrow + sb * 4 + 4);
        fetch4(mv1, trow, fB);
        l2_consume4(fA, m2, s2);
    }
}

__global__ void __launch_bounds__(CTA_THREADS, 1)
snn_kernel(const float* __restrict__ x, const float* __restrict__ W1,
           const float* __restrict__ b1, const float* __restrict__ W2,
           const float* __restrict__ b2, float* __restrict__ out)
{
    extern __shared__ float smem[];
    float* table = smem;                                  // [1024][27] + zero row
    unsigned* maskall = (unsigned*)(smem + TABLE_FLOATS); // [PAIRS][2][68]
    float* stg = smem + TABLE_FLOATS + MASK_U32;          // [PAIRS][2][10][68]

    const int tid  = threadIdx.x;
    const int wid  = tid >> 5;
    const int lane = tid & 31;
    const bool isA = (wid < PAIRS);
    const int pair = wid & (PAIRS - 1);
    const int b = blockIdx.x * PAIRS + pair;

    const float* xb = x + (size_t)b * (6 * T_LEN);

    // Layer-2 lookup table: ascending-n accumulation == reference fma-dot
    // with 0/1 spikes (adding 0.0f is exact).
    for (int e = tid; e < 1024 * 27; e += CTA_THREADS) {
        int v = e / 27;
        int m = e - v * 27;
        float acc = 0.0f;
#pragma unroll
        for (int n = 0; n < 10; n++)
            if (v & (1 << n)) acc = __fadd_rn(acc, W2[m * 10 + n]);
        table[e] = __fadd_rn(acc, b2[m]);
    }
    for (int i = 1024 * 27 + tid; i < TABLE_FLOATS; i += CTA_THREADS)
        table[i] = 0.0f;  // zero row 1024

    unsigned* mbase = maskall + pair * MB_PER_PAIR;
    float* stg0 = stg + pair * STG_PER_PAIR;
    float* stg1 = stg0 + STG_BANK;

    if (isA) {
        // ====== A-warp: layer-1 producer ======
        __syncthreads();  // table + B's chunk-0 staging visible

        float m1 = 0.0f, s1 = 0.0f;
        bool pd = (lane == 10);        // ballot(step -1) = 1<<10 -> zero row
        const bool vlane = (lane < 10);
        const bool st_lane = (lane == 0);
        // lanes >=9 share row 9 (broadcast read, votes masked by vlane)
        const int row = (lane < 9) ? lane : 9;
        const float* rb0 = stg0 + row * STG_ROW;
        const float* rb1 = stg1 + row * STG_ROW;

#pragma unroll 1
        for (int k = 0; k < NCHUNK; k++) {
            const float* rb = (k & 1) ? rb1 : rb0;
            unsigned* mrow = mbase + (k & 1) * MB_BANK;
#pragma unroll
            for (int sb = 0; sb < 16; sb++) {
                float4 c1q = *reinterpret_cast<const float4*>(rb + sb * 4);
                float c1r[4] = {c1q.x, c1q.y, c1q.z, c1q.w};
                unsigned mr[4];
#pragma unroll
                for (int i = 0; i < 4; i++) {
                    mr[i] = __ballot_sync(0xffffffffu, pd);  // lagged: no stall
                    float a1 = fmaf(BETA, m1, c1r[i]);
                    m1 = __fsub_rn(a1, s1);
                    s1 = fset_gt1(m1);
                    pd = (m1 > 1.0f) && vlane;  // sink until next ballot
                }
                if (st_lane)
                    *reinterpret_cast<uint4*>(mrow + sb * 4) =
                        make_uint4(mr[0], mr[1], mr[2], mr[3]);
            }
            if (k == NCHUNK - 1) {  // final mask (step 4095)
                unsigned vf = __ballot_sync(0xffffffffu, pd);
                if (st_lane) mrow[64] = vf;
            }
            PAIR_BAR(pair);
        }
    } else {
        // ====== B-warp: phaseA producer + layer-2 consumer ======
        u64 w12r[5][6], b12r[5];
#pragma unroll
        for (int np = 0; np < 5; np++) {
            b12r[np] = pack2(b1[2 * np], b1[2 * np + 1]);
#pragma unroll
            for (int c = 0; c < 6; c++)
                w12r[np][c] = pack2(W1[(2 * np) * 6 + c], W1[(2 * np + 1) * 6 + c]);
        }
        // chunk 0: columns lane (steps lane) and lane+32 (steps 32+lane)
        float xvA[6], xvB[6];
#pragma unroll
        for (int c = 0; c < 6; c++) {
            xvA[c] = xb[c * T_LEN + lane];
            xvB[c] = xb[c * T_LEN + 32 + lane];
        }
        phaseA_nm(xvA, w12r, b12r, stg0, lane);
        phaseA_nm(xvB, w12r, b12r, stg0, lane + 32);
#pragma unroll
        for (int c = 0; c < 6; c++) {   // x for chunk 1
            xvA[c] = xb[c * T_LEN + 64 + lane];
            xvB[c] = xb[c * T_LEN + 96 + lane];
        }
        __syncthreads();

        const float* trow = table + lane;
        float m2 = 0.0f, s2 = 0.0f;
        float fA[4], fB[4] = {0.0f, 0.0f, 0.0f, 0.0f};  // 4 fake zero steps

#pragma unroll 1
        for (int k = 0; k < NCHUNK; k++) {
            // phaseA for chunk k+1 into the other bank
            if (k < NCHUNK - 1) {
                float* wb = ((k + 1) & 1) ? stg1 : stg0;
                phaseA_nm(xvA, w12r, b12r, wb, lane);
                phaseA_nm(xvB, w12r, b12r, wb, lane + 32);
                int kk = (k + 2 < NCHUNK) ? k + 2 : NCHUNK - 1;  // clamped
#pragma unroll
                for (int c = 0; c < 6; c++) {
                    xvA[c] = xb[c * T_LEN + kk * 64 + lane];
                    xvB[c] = xb[c * T_LEN + kk * 64 + 32 + lane];
                }
            }
            // layer-2 for chunk k-1
            if (k >= 1) {
                const unsigned* mrow = mbase + ((k - 1) & 1) * MB_BANK;
                l2_chunk(mrow, trow, m2, s2, fA, fB);
            }
            PAIR_BAR(pair);
        }
        // Epilogue: chunk 63 (bank 1) + pending + final mask (slot 64)
        {
            const unsigned* mrow = mbase + ((NCHUNK - 1) & 1) * MB_BANK;
            l2_chunk(mrow, trow, m2, s2, fA, fB);
            l2_consume4(fB, m2, s2);              // steps 4091..4094
            float ff = trow[mrow[64] * 27u];      // mask(step 4095)
            float a2 = fmaf(BETA, m2, ff);
            m2 = __fsub_rn(a2, s2);
            s2 = fset_gt1(m2);
        }
        if (lane < 27)
            out[b * 27 + lane] = s2;
    }
}

extern "C" void kernel_launch(void* const* d_in, const int* in_sizes, int n_in,
                              void* d_out, int out_size)
{
    const float* x  = (const float*)d_in[0];
    const float* W1 = (const float*)d_in[1];
    const float* b1 = (const float*)d_in[2];
    const float* W2 = (const float*)d_in[3];
    const float* b2 = (const float*)d_in[4];
    float* out = (float*)d_out;

    cudaFuncSetAttribute(snn_kernel, cudaFuncAttributeMaxDynamicSharedMemorySize,
                         SMEM_BYTES);

    snn_kernel<<<N_CTAS, CTA_THREADS, SMEM_BYTES>>>(x, W1, b1, W2, b2, out);
}